// round 16
// baseline (speedup 1.0000x reference)
#include <cuda_runtime.h>
#include <cuda_fp16.h>

#define S    512
#define NA   180
#define NB   4
#define WS   48
#define HALF_A 90
#define PI_D 3.14159265358979323846

// filtered sinogram, batch-pair fp16: [pair][a][s] = uint2 { half2{em0,em1}, half2{d0,d1} }
// d = rn16(w[s+1]-w[s]),  em = rn16(w[s] + 0.5*float(d))
// sample = em + (fr-0.5)*d = w + fr*d   (f32 arithmetic)
__device__ uint2 g_xfh[2 * NA * S];

// ---------------------------------------------------------------------------
// Stage 1: ramp filter (R14 version). One block per (pair, a): 256 threads =
//   2 batch-halves (bh) x 2 tap-halves (th), 64-thread sliding FIR each.
// ---------------------------------------------------------------------------
#define OFFM(d) ((d) + ((1 + (d)) >> 3))
#define OFFP(d) ((d) + ((7 + (d)) >> 3))

__global__ void __launch_bounds__(256) filter_kernel(const float* __restrict__ x) {
    const int a    = blockIdx.x % NA;
    const int pair = blockIdx.x / NA;

    __shared__ float P[2][1736];
    __shared__ float sg[256];
    __shared__ float sw[2][S + 8];
    __shared__ float sred[2][64][8];

    const int tid = threadIdx.x;
    const int t   = tid & 63;
    const int bh  = (tid >> 6) & 1;
    const int th  = tid >> 7;

    for (int idx = tid; idx < 1024; idx += 256) {
        int bb = idx >> 9, i = idx & 511;
        P[bb][i + (i >> 3)] = 0.0f;
        int j = i + 1024;
        P[bb][j + (j >> 3)] = 0.0f;
    }
    for (int idx = tid; idx < 1024; idx += 256) {
        int bb = idx >> 9, i = idx & 511;
        int ii = i + 512;
        P[bb][ii + (ii >> 3)] = x[((2 * pair + bb) * S + i) * NA + a];
    }
    {
        float dd = (float)(2 * tid + 1);
        if (tid < 256) sg[tid] = -2.0f / ((float)(PI_D * PI_D) * dd * dd);
    }
    __syncthreads();

    float* Pb = P[bh];
    float acc[8];
    if (th == 0) {
        #pragma unroll
        for (int k = 0; k < 8; ++k)
            acc[k] = 0.5f * Pb[9 * t + 576 + k];
    } else {
        #pragma unroll
        for (int k = 0; k < 8; ++k)
            acc[k] = 0.0f;
    }

    float Am[16], Ap[16];
    int A0 = 9 * t + 1 + 288 * th;
    int A1 = 9 * t + 1132 - 288 * th;
    const int sgb = 255 - 128 * th;

    #pragma unroll
    for (int d0 = 0; d0 < 8; ++d0) {
        Am[d0] = Pb[A0 + OFFM(d0)];
        Ap[d0] = Pb[A1 + OFFP(16 + d0)];
    }

    #pragma unroll 1
    for (int g = 0; g < 16; ++g) {
        #pragma unroll
        for (int jj = 0; jj < 8; ++jj) {
            float gc = sg[sgb - 8 * g - jj];
            #pragma unroll
            for (int k = 0; k < 8; ++k) {
                float av = Am[(2 * jj + k) & 15];
                float bv = Ap[(k - 2 * jj) & 15];
                acc[k] = fmaf(gc, av + bv, acc[k]);
            }
            Am[(2 * jj + 8) & 15]  = Pb[A0 + OFFM(2 * jj + 8)];
            Am[(2 * jj + 9) & 15]  = Pb[A0 + OFFM(2 * jj + 9)];
            Ap[(14 - 2 * jj) & 15] = Pb[A1 + OFFP(14 - 2 * jj)];
            Ap[(15 - 2 * jj) & 15] = Pb[A1 + OFFP(15 - 2 * jj)];
        }
        A0 += 18;
        A1 -= 18;
    }

    if (th == 1) {
        #pragma unroll
        for (int k = 0; k < 8; ++k)
            sred[bh][t][k] = acc[k];
    }
    __syncthreads();
    if (th == 0) {
        #pragma unroll
        for (int k = 0; k < 8; ++k)
            sw[bh][8 * t + k] = acc[k] + sred[bh][t][k];
        if (t == 0) sw[bh][S] = 0.0f;
    }
    __syncthreads();

    uint2* o = &g_xfh[(pair * NA + a) * S];
    #pragma unroll
    for (int s = tid; s < S; s += 256) {
        float lo0 = sw[0][s];
        float lo1 = sw[1][s];
        __half d0 = __float2half(sw[0][s + 1] - lo0);
        __half d1 = __float2half(sw[1][s + 1] - lo1);
        __half e0 = __float2half(fmaf(0.5f, __half2float(d0), lo0));
        __half e1 = __float2half(fmaf(0.5f, __half2float(d1), lo1));
        __half2 eh = __halves2half2(e0, e1);
        __half2 dh = __halves2half2(d0, d1);
        uint2 v;
        v.x = *(unsigned*)&eh;
        v.y = *(unsigned*)&dh;
        o[s] = v;
    }
}

// ---------------------------------------------------------------------------
// Stage 2: backprojection, fp16 storage / f32 arithmetic, packed E-accum,
// 32x32 tiles x 4 y-slots -> 512 blocks = SINGLE WAVE at 5 blocks/SM.
// Grid (16,16,2). 256 threads, slots yb + {0,8,16,24}.
// ---------------------------------------------------------------------------
__global__ void __launch_bounds__(256, 5) backproj_kernel(float* __restrict__ out) {
    __shared__ uint2  winh[HALF_A * WS];     // 34560 B
    __shared__ float4 consA[NA];             // {cs, czb, ns, 8ns}
    __shared__ int    w0s[NA];

    const int tid  = threadIdx.x;
    const int pair = blockIdx.z;
    const int x0   = blockIdx.x * 32;
    const int y0   = blockIdx.y * 32;

    const int lane = tid & 31;
    const int w    = tid >> 5;
    const int x    = ((w & 3) << 3) + (lane & 7);        // 0..31
    const int yb   = (lane >> 3) + ((w >> 2) << 2);      // 0..7 (slots +8k)

    const int b0 = 2 * pair, b1 = 2 * pair + 1;
    const float invh = 2.0f / 511.0f;

    // ---- early out: tile fully outside the unit circle ----
    {
        float ux0 = fmaf((float)x0,        invh, -1.0f);
        float ux1 = fmaf((float)(x0 + 31), invh, -1.0f);
        float uy0 = fmaf((float)y0,        invh, -1.0f);
        float uy1 = fmaf((float)(y0 + 31), invh, -1.0f);
        float mx = (ux0 <= 0.0f && ux1 >= 0.0f) ? 0.0f : fminf(fabsf(ux0), fabsf(ux1));
        float my = (uy0 <= 0.0f && uy1 >= 0.0f) ? 0.0f : fminf(fabsf(uy0), fabsf(uy1));
        if (mx * mx + my * my > 1.0f) {
            #pragma unroll
            for (int k = 0; k < 4; ++k) {
                int y = y0 + yb + 8 * k;
                out[(b0 * S + y) * S + x0 + x] = 0.0f;
                out[(b1 * S + y) * S + x0 + x] = 0.0f;
            }
            return;
        }
    }

    // ---- per-angle tables ----
    if (tid < NA) {
        float th = (float)tid * (float)(PI_D / 180.0);
        float sn, cs;
        sincosf(th, &sn, &cs);
        float pb = 255.5f + ((float)x0 - 255.5f) * cs - ((float)y0 - 255.5f) * sn;
        float pmin = pb + fminf(cs * 31.0f, 0.0f) + fminf(-sn * 31.0f, 0.0f);
        int w0 = (int)floorf(pmin) - 1;          // local p in [1, ~45.9)
        w0s[tid] = w0;
        float ns = -sn;
        consA[tid] = make_float4(cs, pb - (float)w0 + 1024.0f, ns, 8.0f * ns);
    }
    __syncthreads();

    const float FX = (float)x;
    const float FY = (float)yb;

    // addr = (bits>>13)*8 + wb ; bits>>13 = 0x22400 + idx -> wb0 = base - 0x112000
    const unsigned wbadj = (unsigned)__cvta_generic_to_shared(winh) - 0x112000u;
    const unsigned cA0 = (unsigned)__cvta_generic_to_shared(consA);

    unsigned long long accE0 = 0, accE1 = 0, accE2 = 0, accE3 = 0;
    float aF00 = 0.f, aF01 = 0.f;               // slot0 batches
    float aF10 = 0.f, aF11 = 0.f;               // slot1
    float aF20 = 0.f, aF21 = 0.f;               // slot2
    float aF30 = 0.f, aF31 = 0.f;               // slot3

    const uint2* __restrict__ gw = &g_xfh[pair * NA * S];

    const int al = (tid < 240) ? tid / WS : 0;     // 0..4
    const int oo = tid - al * WS;

#define SLOT_ACC(FM, EE, DD, ACCE, AF0, AF1)                                  \
            asm("{\n\t"                                                       \
                ".reg .b16 hl, hh;\n\t"                                       \
                ".reg .f32 f0, f1, g0, g1;\n\t"                               \
                ".reg .b64 eP;\n\t"                                           \
                "mov.b32 {hl, hh}, %3;\n\t"                                   \
                "cvt.f32.f16 f0, hl;\n\t"                                     \
                "cvt.f32.f16 f1, hh;\n\t"                                     \
                "mov.b64 eP, {f0, f1};\n\t"                                   \
                "add.rn.f32x2 %0, %0, eP;\n\t"                                \
                "mov.b32 {hl, hh}, %4;\n\t"                                   \
                "cvt.f32.f16 g0, hl;\n\t"                                     \
                "cvt.f32.f16 g1, hh;\n\t"                                     \
                "fma.rn.f32 %1, %5, g0, %1;\n\t"                              \
                "fma.rn.f32 %2, %5, g1, %2;\n\t"                              \
                "}"                                                           \
                : "+l"(ACCE), "+f"(AF0), "+f"(AF1)                            \
                : "r"(EE), "r"(DD), "f"(FM));

#define ANGLE(CIMM, WIMM)                                                     \
        {                                                                     \
            unsigned a0, a1, a2, a3;                                          \
            float fm0, fm1, fm2, fm3;                                         \
            asm("{\n\t"                                                       \
                ".reg .f32 cs, czb, ns, ns8, bx, p0f, p1f, p2f, p3f, ft;\n\t" \
                ".reg .b32 rb, rt;\n\t"                                       \
                "ld.shared.v4.f32 {cs, czb, ns, ns8}, [%8+" #CIMM "];\n\t"    \
                "fma.rn.f32 bx, cs, %9, czb;\n\t"                             \
                "fma.rn.f32 p0f, ns, %10, bx;\n\t"                            \
                "add.rn.f32 p1f, p0f, ns8;\n\t"                               \
                "add.rn.f32 p2f, p1f, ns8;\n\t"                               \
                "add.rn.f32 p3f, p2f, ns8;\n\t"                               \
                "mov.b32 rb, p0f;\n\t"                                        \
                "shr.u32 rt, rb, 13;\n\t"                                     \
                "mad.lo.u32 %0, rt, 8, %11;\n\t"                              \
                "shl.b32 rt, rb, 10;\n\t"                                     \
                "lop3.b32 rt, rt, 0x007FFC00, 0x3F800000, 0xEA;\n\t"          \
                "mov.b32 ft, rt;\n\t"                                         \
                "sub.rn.f32 %4, ft, 0f3FC00000;\n\t"                          \
                "mov.b32 rb, p1f;\n\t"                                        \
                "shr.u32 rt, rb, 13;\n\t"                                     \
                "mad.lo.u32 %1, rt, 8, %11;\n\t"                              \
                "shl.b32 rt, rb, 10;\n\t"                                     \
                "lop3.b32 rt, rt, 0x007FFC00, 0x3F800000, 0xEA;\n\t"          \
                "mov.b32 ft, rt;\n\t"                                         \
                "sub.rn.f32 %5, ft, 0f3FC00000;\n\t"                          \
                "mov.b32 rb, p2f;\n\t"                                        \
                "shr.u32 rt, rb, 13;\n\t"                                     \
                "mad.lo.u32 %2, rt, 8, %11;\n\t"                              \
                "shl.b32 rt, rb, 10;\n\t"                                     \
                "lop3.b32 rt, rt, 0x007FFC00, 0x3F800000, 0xEA;\n\t"          \
                "mov.b32 ft, rt;\n\t"                                         \
                "sub.rn.f32 %6, ft, 0f3FC00000;\n\t"                          \
                "mov.b32 rb, p3f;\n\t"                                        \
                "shr.u32 rt, rb, 13;\n\t"                                     \
                "mad.lo.u32 %3, rt, 8, %11;\n\t"                              \
                "shl.b32 rt, rb, 10;\n\t"                                     \
                "lop3.b32 rt, rt, 0x007FFC00, 0x3F800000, 0xEA;\n\t"          \
                "mov.b32 ft, rt;\n\t"                                         \
                "sub.rn.f32 %7, ft, 0f3FC00000;\n\t"                          \
                "}"                                                           \
                : "=&r"(a0), "=&r"(a1), "=&r"(a2), "=&r"(a3),                 \
                  "=&f"(fm0), "=&f"(fm1), "=&f"(fm2), "=&f"(fm3)              \
                : "r"(caA), "f"(FX), "f"(FY), "r"(wb));                       \
            unsigned E0, D0, E1, D1, E2, D2, E3, D3;                          \
            asm volatile("ld.shared.v2.b32 {%0, %1}, [%2+" #WIMM "];"         \
                         : "=r"(E0), "=r"(D0) : "r"(a0));                     \
            asm volatile("ld.shared.v2.b32 {%0, %1}, [%2+" #WIMM "];"         \
                         : "=r"(E1), "=r"(D1) : "r"(a1));                     \
            asm volatile("ld.shared.v2.b32 {%0, %1}, [%2+" #WIMM "];"         \
                         : "=r"(E2), "=r"(D2) : "r"(a2));                     \
            asm volatile("ld.shared.v2.b32 {%0, %1}, [%2+" #WIMM "];"         \
                         : "=r"(E3), "=r"(D3) : "r"(a3));                     \
            SLOT_ACC(fm0, E0, D0, accE0, aF00, aF01)                          \
            SLOT_ACC(fm1, E1, D1, accE1, aF10, aF11)                          \
            SLOT_ACC(fm2, E2, D2, accE2, aF20, aF21)                          \
            SLOT_ACC(fm3, E3, D3, accE3, aF30, aF31)                          \
        }

    #pragma unroll 1
    for (int phase = 0; phase < 2; ++phase) {
        const int abase = phase * HALF_A;

        // ---- cooperative window fill (straight uint2 copy) ----
        if (tid < 240) {
            #pragma unroll
            for (int ar = al; ar < HALF_A; ar += 5) {
                int a  = abase + ar;
                int gi = w0s[a] + oo;
                uint2 v;
                if ((unsigned)gi < (unsigned)S) {
                    v = gw[a * S + gi];
                } else if (gi == -1) {
                    // bin -1 interpolates 0 -> w[0]:  d = rn(w0), em = rn(0.5*d)
                    uint2 v0 = gw[a * S];
                    __half2 e2 = *(__half2*)&v0.x;
                    __half2 d2 = *(__half2*)&v0.y;
                    float w00 = __low2float(e2)  - 0.5f * __low2float(d2);
                    float w01 = __high2float(e2) - 0.5f * __high2float(d2);
                    __half2 nd = __floats2half2_rn(w00, w01);
                    __half2 ne = __floats2half2_rn(0.5f * __low2float(nd),
                                                   0.5f * __high2float(nd));
                    v.x = *(unsigned*)&ne;
                    v.y = *(unsigned*)&nd;
                } else {
                    v.x = 0u; v.y = 0u;
                }
                winh[ar * WS + oo] = v;
            }
        }
        __syncthreads();

        unsigned caA = cA0 + (unsigned)abase * 16u;
        unsigned wb  = wbadj;

        #pragma unroll 1
        for (int ch = 0; ch < 15; ++ch) {      // 15 chunks x 6 angles = 90
            ANGLE(0,  0)
            ANGLE(16, 384)
            ANGLE(32, 768)
            ANGLE(48, 1152)
            ANGLE(64, 1536)
            ANGLE(80, 1920)
            caA += 96u;
            wb  += 2304u;                       // 6 * WS * 8
        }
        __syncthreads();
    }
#undef ANGLE
#undef SLOT_ACC

    // ---- unpack, mask, scale, store (both batches) ----
    const float scale = (float)(PI_D / (2.0 * NA));
    const float ux  = fmaf((float)(x0 + x), invh, -1.0f);
    const float uxx = ux * ux;

#define STORE_SLOT(ACCE, AF0, AF1, K)                                         \
    {                                                                         \
        float e0, e1;                                                         \
        asm("mov.b64 {%0, %1}, %2;" : "=f"(e0), "=f"(e1) : "l"(ACCE));        \
        int y = y0 + yb + 8 * (K);                                            \
        float uy = fmaf((float)y, invh, -1.0f);                               \
        bool in = (uxx + uy * uy <= 1.0f);                                    \
        out[(b0 * S + y) * S + x0 + x] = in ? (e0 + AF0) * scale : 0.0f;      \
        out[(b1 * S + y) * S + x0 + x] = in ? (e1 + AF1) * scale : 0.0f;      \
    }

    STORE_SLOT(accE0, aF00, aF01, 0)
    STORE_SLOT(accE1, aF10, aF11, 1)
    STORE_SLOT(accE2, aF20, aF21, 2)
    STORE_SLOT(accE3, aF30, aF31, 3)
#undef STORE_SLOT
}

// ---------------------------------------------------------------------------
extern "C" void kernel_launch(void* const* d_in, const int* in_sizes, int n_in,
                              void* d_out, int out_size) {
    const float* x = (const float*)d_in[0];
    float* out = (float*)d_out;

    filter_kernel<<<2 * NA, 256>>>(x);

    dim3 grid(16, 16, 2);
    backproj_kernel<<<grid, 256>>>(out);
}

// round 17
// speedup vs baseline: 1.1550x; 1.1550x over previous
#include <cuda_runtime.h>
#include <cuda_fp16.h>

#define S    512
#define NA   180
#define NB   4
#define WS   38
#define HALF_A 90
#define PI_D 3.14159265358979323846

// filtered sinogram, batch-pair fp16: [pair][a][s] = uint2 { half2{em0,em1}, half2{d0,d1} }
// d = rn16(w[s+1]-w[s]),  em = rn16(w[s] + 0.5*float(d))
// sample = em + (fr-0.5)*d = w + fr*d   (f32 arithmetic)
__device__ uint2 g_xfh[2 * NA * S];

// ---------------------------------------------------------------------------
// Stage 1: ramp filter (R14 version). One block per (pair, a): 256 threads =
//   2 batch-halves (bh) x 2 tap-halves (th), 64-thread sliding FIR each.
// ---------------------------------------------------------------------------
#define OFFM(d) ((d) + ((1 + (d)) >> 3))
#define OFFP(d) ((d) + ((7 + (d)) >> 3))

__global__ void __launch_bounds__(256) filter_kernel(const float* __restrict__ x) {
    const int a    = blockIdx.x % NA;
    const int pair = blockIdx.x / NA;

    __shared__ float P[2][1736];
    __shared__ float sg[256];
    __shared__ float sw[2][S + 8];
    __shared__ float sred[2][64][8];

    const int tid = threadIdx.x;
    const int t   = tid & 63;
    const int bh  = (tid >> 6) & 1;
    const int th  = tid >> 7;

    for (int idx = tid; idx < 1024; idx += 256) {
        int bb = idx >> 9, i = idx & 511;
        P[bb][i + (i >> 3)] = 0.0f;
        int j = i + 1024;
        P[bb][j + (j >> 3)] = 0.0f;
    }
    for (int idx = tid; idx < 1024; idx += 256) {
        int bb = idx >> 9, i = idx & 511;
        int ii = i + 512;
        P[bb][ii + (ii >> 3)] = x[((2 * pair + bb) * S + i) * NA + a];
    }
    {
        float dd = (float)(2 * tid + 1);
        if (tid < 256) sg[tid] = -2.0f / ((float)(PI_D * PI_D) * dd * dd);
    }
    __syncthreads();

    float* Pb = P[bh];
    float acc[8];
    if (th == 0) {
        #pragma unroll
        for (int k = 0; k < 8; ++k)
            acc[k] = 0.5f * Pb[9 * t + 576 + k];
    } else {
        #pragma unroll
        for (int k = 0; k < 8; ++k)
            acc[k] = 0.0f;
    }

    float Am[16], Ap[16];
    int A0 = 9 * t + 1 + 288 * th;
    int A1 = 9 * t + 1132 - 288 * th;
    const int sgb = 255 - 128 * th;

    #pragma unroll
    for (int d0 = 0; d0 < 8; ++d0) {
        Am[d0] = Pb[A0 + OFFM(d0)];
        Ap[d0] = Pb[A1 + OFFP(16 + d0)];
    }

    #pragma unroll 1
    for (int g = 0; g < 16; ++g) {
        #pragma unroll
        for (int jj = 0; jj < 8; ++jj) {
            float gc = sg[sgb - 8 * g - jj];
            #pragma unroll
            for (int k = 0; k < 8; ++k) {
                float av = Am[(2 * jj + k) & 15];
                float bv = Ap[(k - 2 * jj) & 15];
                acc[k] = fmaf(gc, av + bv, acc[k]);
            }
            Am[(2 * jj + 8) & 15]  = Pb[A0 + OFFM(2 * jj + 8)];
            Am[(2 * jj + 9) & 15]  = Pb[A0 + OFFM(2 * jj + 9)];
            Ap[(14 - 2 * jj) & 15] = Pb[A1 + OFFP(14 - 2 * jj)];
            Ap[(15 - 2 * jj) & 15] = Pb[A1 + OFFP(15 - 2 * jj)];
        }
        A0 += 18;
        A1 -= 18;
    }

    if (th == 1) {
        #pragma unroll
        for (int k = 0; k < 8; ++k)
            sred[bh][t][k] = acc[k];
    }
    __syncthreads();
    if (th == 0) {
        #pragma unroll
        for (int k = 0; k < 8; ++k)
            sw[bh][8 * t + k] = acc[k] + sred[bh][t][k];
        if (t == 0) sw[bh][S] = 0.0f;
    }
    __syncthreads();

    uint2* o = &g_xfh[(pair * NA + a) * S];
    #pragma unroll
    for (int s = tid; s < S; s += 256) {
        float lo0 = sw[0][s];
        float lo1 = sw[1][s];
        __half d0 = __float2half(sw[0][s + 1] - lo0);
        __half d1 = __float2half(sw[1][s + 1] - lo1);
        __half e0 = __float2half(fmaf(0.5f, __half2float(d0), lo0));
        __half e1 = __float2half(fmaf(0.5f, __half2float(d1), lo1));
        __half2 eh = __halves2half2(e0, e1);
        __half2 dh = __halves2half2(d0, d1);
        uint2 v;
        v.x = *(unsigned*)&eh;
        v.y = *(unsigned*)&dh;
        o[s] = v;
    }
}

// ---------------------------------------------------------------------------
// Stage 2: backprojection, fp16 storage / f32 arithmetic, packed E-accum,
// ANGLE-PAIR packed front-end (f32x2 == two scalar fmas, bit-identical).
// Grid (16,32,2): 32x16 tile x one batch PAIR. 256 threads, 2 y-slots each.
// ---------------------------------------------------------------------------
__global__ void __launch_bounds__(256, 6) backproj_kernel(float* __restrict__ out) {
    __shared__ uint2  winh[HALF_A * WS];     // 27360 B
    __shared__ float4 consP[2 * HALF_A];     // [k]={cs,cs',czb,czb'} [90+k]={ns,ns',8ns,8ns'}
    __shared__ int    w0s[NA];

    const int tid  = threadIdx.x;
    const int pair = blockIdx.z;
    const int x0   = blockIdx.x * 32;
    const int y0   = blockIdx.y * 16;

    const int lane = tid & 31;
    const int w    = tid >> 5;
    const int x    = ((w & 3) << 3) + (lane & 7);        // 0..31
    const int yb   = (lane >> 3) + ((w >> 2) << 2);      // 0..7 (slots yb, yb+8)

    const int b0 = 2 * pair, b1 = 2 * pair + 1;
    const float invh = 2.0f / 511.0f;

    // ---- early out: tile fully outside the unit circle ----
    {
        float ux0 = fmaf((float)x0,        invh, -1.0f);
        float ux1 = fmaf((float)(x0 + 31), invh, -1.0f);
        float uy0 = fmaf((float)y0,        invh, -1.0f);
        float uy1 = fmaf((float)(y0 + 15), invh, -1.0f);
        float mx = (ux0 <= 0.0f && ux1 >= 0.0f) ? 0.0f : fminf(fabsf(ux0), fabsf(ux1));
        float my = (uy0 <= 0.0f && uy1 >= 0.0f) ? 0.0f : fminf(fabsf(uy0), fabsf(uy1));
        if (mx * mx + my * my > 1.0f) {
            #pragma unroll
            for (int k = 0; k < 2; ++k) {
                int y = y0 + yb + 8 * k;
                out[(b0 * S + y) * S + x0 + x] = 0.0f;
                out[(b1 * S + y) * S + x0 + x] = 0.0f;
            }
            return;
        }
    }

    // ---- per-angle-pair tables (thread k handles angles 2k, 2k+1) ----
    if (tid < HALF_A) {
        float cs2[2], czb2[2], ns2[2];
        #pragma unroll
        for (int j = 0; j < 2; ++j) {
            int a = 2 * tid + j;
            float th = (float)a * (float)(PI_D / 180.0);
            float sn, cs;
            sincosf(th, &sn, &cs);
            float pb = 255.5f + ((float)x0 - 255.5f) * cs - ((float)y0 - 255.5f) * sn;
            float pmin = pb + fminf(cs * 31.0f, 0.0f) + fminf(-sn * 15.0f, 0.0f);
            int w0 = (int)floorf(pmin) - 1;      // local p in [1, ~36.5)
            w0s[a] = w0;
            cs2[j]  = cs;
            czb2[j] = pb - (float)w0 + 1024.0f;
            ns2[j]  = -sn;
        }
        consP[tid]          = make_float4(cs2[0], cs2[1], czb2[0], czb2[1]);
        consP[HALF_A + tid] = make_float4(ns2[0], ns2[1], 8.0f * ns2[0], 8.0f * ns2[1]);
    }
    __syncthreads();

    unsigned long long FX2, FY2;
    {
        float fx = (float)x, fy = (float)yb;
        asm("mov.b64 %0, {%1, %1};" : "=l"(FX2) : "f"(fx));
        asm("mov.b64 %0, {%1, %1};" : "=l"(FY2) : "f"(fy));
    }

    // addr = (bits>>13)*8 + wb ; bits>>13 = 0x22400 + idx -> wb0 = base - 0x112000
    const unsigned wbadj = (unsigned)__cvta_generic_to_shared(winh) - 0x112000u;
    const unsigned cP0 = (unsigned)__cvta_generic_to_shared(consP);

    unsigned long long accE0 = 0, accE1 = 0;    // packed {E_b0, E_b1} per slot
    float aF00 = 0.f, aF01 = 0.f;               // slot0: fm*d accums per batch
    float aF10 = 0.f, aF11 = 0.f;               // slot1

    const uint2* __restrict__ gw = &g_xfh[pair * NA * S];

    const int al = (tid < 228) ? tid / WS : 0;     // 0..5
    const int oo = tid - al * WS;

#define SLOT_ACC(FM, EE, DD, ACCE, AF0, AF1)                                  \
            asm("{\n\t"                                                       \
                ".reg .b16 hl, hh;\n\t"                                       \
                ".reg .f32 f0, f1, g0, g1;\n\t"                               \
                ".reg .b64 eP;\n\t"                                           \
                "mov.b32 {hl, hh}, %3;\n\t"                                   \
                "cvt.f32.f16 f0, hl;\n\t"                                     \
                "cvt.f32.f16 f1, hh;\n\t"                                     \
                "mov.b64 eP, {f0, f1};\n\t"                                   \
                "add.rn.f32x2 %0, %0, eP;\n\t"                                \
                "mov.b32 {hl, hh}, %4;\n\t"                                   \
                "cvt.f32.f16 g0, hl;\n\t"                                     \
                "cvt.f32.f16 g1, hh;\n\t"                                     \
                "fma.rn.f32 %1, %5, g0, %1;\n\t"                              \
                "fma.rn.f32 %2, %5, g1, %2;\n\t"                              \
                "}"                                                           \
                : "+l"(ACCE), "+f"(AF0), "+f"(AF1)                            \
                : "r"(EE), "r"(DD), "f"(FM));

// One PAIR of angles (A = pair base, B = A+1) for both slots.
// PIMM: byte offset of consP[k] in chunk; WA: window row byte offset of angle A.
#define ANGLE2(PIMM, P2IMM, WA, WB)                                           \
        {                                                                     \
            unsigned qa0, qa1, qb0, qb1;                                      \
            float fa0, fa1, fb0, fb1;                                         \
            asm("{\n\t"                                                       \
                ".reg .b64 CS2, CZ2, NS2, N82, BX2, P0, P1;\n\t"              \
                ".reg .f32 pa0, pb0, pa1, pb1, ft;\n\t"                       \
                ".reg .b32 rb, rt;\n\t"                                       \
                "ld.shared.v2.b64 {CS2, CZ2}, [%8+" #PIMM "];\n\t"            \
                "ld.shared.v2.b64 {NS2, N82}, [%8+" #P2IMM "];\n\t"           \
                "fma.rn.f32x2 BX2, CS2, %9, CZ2;\n\t"                         \
                "fma.rn.f32x2 P0, NS2, %10, BX2;\n\t"                         \
                "add.rn.f32x2 P1, P0, N82;\n\t"                               \
                "mov.b64 {pa0, pb0}, P0;\n\t"                                 \
                "mov.b64 {pa1, pb1}, P1;\n\t"                                 \
                "mov.b32 rb, pa0;\n\t"                                        \
                "shr.u32 rt, rb, 13;\n\t"                                     \
                "mad.lo.u32 %0, rt, 8, %11;\n\t"                              \
                "shl.b32 rt, rb, 10;\n\t"                                     \
                "lop3.b32 rt, rt, 0x007FFC00, 0x3F800000, 0xEA;\n\t"          \
                "mov.b32 ft, rt;\n\t"                                         \
                "sub.rn.f32 %4, ft, 0f3FC00000;\n\t"                          \
                "mov.b32 rb, pa1;\n\t"                                        \
                "shr.u32 rt, rb, 13;\n\t"                                     \
                "mad.lo.u32 %1, rt, 8, %11;\n\t"                              \
                "shl.b32 rt, rb, 10;\n\t"                                     \
                "lop3.b32 rt, rt, 0x007FFC00, 0x3F800000, 0xEA;\n\t"          \
                "mov.b32 ft, rt;\n\t"                                         \
                "sub.rn.f32 %5, ft, 0f3FC00000;\n\t"                          \
                "mov.b32 rb, pb0;\n\t"                                        \
                "shr.u32 rt, rb, 13;\n\t"                                     \
                "mad.lo.u32 %2, rt, 8, %11;\n\t"                              \
                "shl.b32 rt, rb, 10;\n\t"                                     \
                "lop3.b32 rt, rt, 0x007FFC00, 0x3F800000, 0xEA;\n\t"          \
                "mov.b32 ft, rt;\n\t"                                         \
                "sub.rn.f32 %6, ft, 0f3FC00000;\n\t"                          \
                "mov.b32 rb, pb1;\n\t"                                        \
                "shr.u32 rt, rb, 13;\n\t"                                     \
                "mad.lo.u32 %3, rt, 8, %11;\n\t"                              \
                "shl.b32 rt, rb, 10;\n\t"                                     \
                "lop3.b32 rt, rt, 0x007FFC00, 0x3F800000, 0xEA;\n\t"          \
                "mov.b32 ft, rt;\n\t"                                         \
                "sub.rn.f32 %7, ft, 0f3FC00000;\n\t"                          \
                "}"                                                           \
                : "=&r"(qa0), "=&r"(qa1), "=&r"(qb0), "=&r"(qb1),             \
                  "=&f"(fa0), "=&f"(fa1), "=&f"(fb0), "=&f"(fb1)              \
                : "r"(caP), "l"(FX2), "l"(FY2), "r"(wb));                     \
            unsigned EA0, DA0, EA1, DA1, EB0, DB0, EB1, DB1;                  \
            asm volatile("ld.shared.v2.b32 {%0, %1}, [%2+" #WA "];"           \
                         : "=r"(EA0), "=r"(DA0) : "r"(qa0));                  \
            asm volatile("ld.shared.v2.b32 {%0, %1}, [%2+" #WA "];"           \
                         : "=r"(EA1), "=r"(DA1) : "r"(qa1));                  \
            asm volatile("ld.shared.v2.b32 {%0, %1}, [%2+" #WB "];"           \
                         : "=r"(EB0), "=r"(DB0) : "r"(qb0));                  \
            asm volatile("ld.shared.v2.b32 {%0, %1}, [%2+" #WB "];"           \
                         : "=r"(EB1), "=r"(DB1) : "r"(qb1));                  \
            SLOT_ACC(fa0, EA0, DA0, accE0, aF00, aF01)                        \
            SLOT_ACC(fa1, EA1, DA1, accE1, aF10, aF11)                        \
            SLOT_ACC(fb0, EB0, DB0, accE0, aF00, aF01)                        \
            SLOT_ACC(fb1, EB1, DB1, accE1, aF10, aF11)                        \
        }

    #pragma unroll 1
    for (int phase = 0; phase < 2; ++phase) {
        const int abase = phase * HALF_A;

        // ---- cooperative window fill (straight uint2 copy) ----
        if (tid < 228) {
            #pragma unroll
            for (int ar = al; ar < HALF_A; ar += 6) {
                int a  = abase + ar;
                int gi = w0s[a] + oo;
                uint2 v;
                if ((unsigned)gi < (unsigned)S) {
                    v = gw[a * S + gi];
                } else if (gi == -1) {
                    // bin -1 interpolates 0 -> w[0]:  d = rn(w0), em = rn(0.5*d)
                    uint2 v0 = gw[a * S];
                    __half2 e2 = *(__half2*)&v0.x;
                    __half2 d2 = *(__half2*)&v0.y;
                    float w00 = __low2float(e2)  - 0.5f * __low2float(d2);
                    float w01 = __high2float(e2) - 0.5f * __high2float(d2);
                    __half2 nd = __floats2half2_rn(w00, w01);
                    __half2 ne = __floats2half2_rn(0.5f * __low2float(nd),
                                                   0.5f * __high2float(nd));
                    v.x = *(unsigned*)&ne;
                    v.y = *(unsigned*)&nd;
                } else {
                    v.x = 0u; v.y = 0u;
                }
                winh[ar * WS + oo] = v;
            }
        }
        __syncthreads();

        // pairs for this phase: k = abase/2 .. abase/2 + 44
        unsigned caP = cP0 + (unsigned)(abase / 2) * 16u;
        unsigned wb  = wbadj;

        #pragma unroll 1
        for (int ch = 0; ch < 15; ++ch) {      // 15 chunks x 3 pairs = 45 pairs
            ANGLE2(0,  1440, 0,    304)
            ANGLE2(16, 1456, 608,  912)
            ANGLE2(32, 1472, 1216, 1520)
            caP += 48u;
            wb  += 1824u;                       // 6 angles * WS * 8
        }
        __syncthreads();
    }
#undef ANGLE2
#undef SLOT_ACC

    // ---- unpack, mask, scale, store (both batches) ----
    const float scale = (float)(PI_D / (2.0 * NA));
    const float ux  = fmaf((float)(x0 + x), invh, -1.0f);
    const float uxx = ux * ux;

    {
        float e0, e1;
        asm("mov.b64 {%0, %1}, %2;" : "=f"(e0), "=f"(e1) : "l"(accE0));
        int y = y0 + yb;
        float uy = fmaf((float)y, invh, -1.0f);
        bool in = (uxx + uy * uy <= 1.0f);
        out[(b0 * S + y) * S + x0 + x] = in ? (e0 + aF00) * scale : 0.0f;
        out[(b1 * S + y) * S + x0 + x] = in ? (e1 + aF01) * scale : 0.0f;
    }
    {
        float e0, e1;
        asm("mov.b64 {%0, %1}, %2;" : "=f"(e0), "=f"(e1) : "l"(accE1));
        int y = y0 + yb + 8;
        float uy = fmaf((float)y, invh, -1.0f);
        bool in = (uxx + uy * uy <= 1.0f);
        out[(b0 * S + y) * S + x0 + x] = in ? (e0 + aF10) * scale : 0.0f;
        out[(b1 * S + y) * S + x0 + x] = in ? (e1 + aF11) * scale : 0.0f;
    }
}

// ---------------------------------------------------------------------------
extern "C" void kernel_launch(void* const* d_in, const int* in_sizes, int n_in,
                              void* d_out, int out_size) {
    const float* x = (const float*)d_in[0];
    float* out = (float*)d_out;

    filter_kernel<<<2 * NA, 256>>>(x);

    dim3 grid(16, 32, 2);
    backproj_kernel<<<grid, 256>>>(out);
}